// round 1
// baseline (speedup 1.0000x reference)
#include <cuda_runtime.h>
#include <stdint.h>

// Stable counting sort by tile_id (<=256 bins) using per-thread-segment histograms.
// T_TOTAL threads each own a contiguous segment of <=SEG points; processing each
// segment sequentially preserves input order within a segment, and the
// (bin-major, segment-minor) exclusive scan preserves order across segments ->
// fully stable, matching jnp.argsort(stable).

#define T_TOTAL 16384
#define BLK     128
#define GRID    (T_TOTAL / BLK)   // 128 blocks
#define NBIN    256
#define MAXN    2000000

__device__ unsigned char g_tile8[MAXN];
__device__ unsigned char g_hist8[NBIN * T_TOTAL];      // [bin][thread]
__device__ unsigned int  g_base [NBIN * T_TOTAL];      // exclusive prefix within bin
__device__ int g_counts [NBIN];
__device__ int g_offsets[NBIN];

// ---------------- K1: tile id per point (coalesced) ----------------
__global__ void k1_tile(const float2* __restrict__ pos, const int* __restrict__ pnum, int N) {
    int i = blockIdx.x * blockDim.x + threadIdx.x;
    if (i >= N) return;
    int num_tile = *pnum;
    float ts = 1024.0f / (float)num_tile;
    float2 p = pos[i];
    int tx = (int)floorf(p.x / ts);
    int ty = (int)floorf(p.y / ts);
    tx = min(max(tx, 0), num_tile - 1);
    ty = min(max(ty, 0), num_tile - 1);
    g_tile8[i] = (unsigned char)(ty * num_tile + tx);
}

// ---------------- K2: per-thread-segment histogram ----------------
__global__ void k2_hist(int N, int SEG) {
    __shared__ unsigned char sh[NBIN * BLK];   // 32KB: sh[bin*BLK + tid]
    int tid = threadIdx.x;
    uint32_t* shw = (uint32_t*)sh;
    for (int i = tid; i < NBIN * BLK / 4; i += BLK) shw[i] = 0u;
    __syncthreads();
    int g = blockIdx.x * BLK + tid;
    int s = g * SEG;
    int e = min(s + SEG, N);
    for (int p = s; p < e; p++) {
        sh[(int)g_tile8[p] * BLK + tid]++;
    }
    __syncthreads();
    // write column: coalesced across tid
    for (int b = 0; b < NBIN; b++) {
        g_hist8[b * T_TOTAL + g] = sh[b * BLK + tid];
    }
}

// ---------------- K5: per-bin exclusive scan across segments + tile_counts ----------------
__global__ void k5_scan(const int* __restrict__ pnum, int N, float* __restrict__ out) {
    int nt = (*pnum) * (*pnum);
    int bin = blockIdx.x;
    if (bin >= nt) return;
    const int ITEMS = T_TOTAL / 256;   // 64
    int tid = threadIdx.x;
    const unsigned char* src = &g_hist8[bin * T_TOTAL + tid * ITEMS];
    int sum = 0;
    #pragma unroll 16
    for (int j = 0; j < ITEMS; j++) sum += src[j];
    __shared__ int sh[256];
    sh[tid] = sum;
    __syncthreads();
    for (int off = 1; off < 256; off <<= 1) {
        int x = (tid >= off) ? sh[tid - off] : 0;
        __syncthreads();
        sh[tid] += x;
        __syncthreads();
    }
    unsigned int run = (unsigned int)(sh[tid] - sum);  // exclusive
    unsigned int* dst = &g_base[bin * T_TOTAL + tid * ITEMS];
    #pragma unroll 16
    for (int j = 0; j < ITEMS; j++) {
        dst[j] = run;
        run += src[j];
    }
    if (tid == 255) {
        g_counts[bin] = sh[255];
        out[7ull * (unsigned long long)N + bin] = (float)sh[255];
    }
}

// ---------------- K4: exclusive scan over bins -> tile_offsets ----------------
__global__ void k4_off(const int* __restrict__ pnum, int N, float* __restrict__ out) {
    int nt = (*pnum) * (*pnum);
    int tid = threadIdx.x;
    int v = (tid < nt) ? g_counts[tid] : 0;
    __shared__ int sh[256];
    sh[tid] = v;
    __syncthreads();
    for (int off = 1; off < 256; off <<= 1) {
        int x = (tid >= off) ? sh[tid - off] : 0;
        __syncthreads();
        sh[tid] += x;
        __syncthreads();
    }
    int excl = sh[tid] - v;
    if (tid < nt) {
        g_offsets[tid] = excl;
        out[7ull * (unsigned long long)N + nt + tid] = (float)excl;
    }
}

// ---------------- K6: stable scatter + feature computation ----------------
__global__ void k6_scatter(const float2* __restrict__ pos,
                           const float4* __restrict__ cov,
                           const float* __restrict__ opac,
                           const int* __restrict__ pnum,
                           int N, int SEG, float* __restrict__ out) {
    __shared__ unsigned char run8[NBIN * BLK];  // 32KB running counters
    __shared__ int soff[NBIN];
    int tid = threadIdx.x;
    int nt = (*pnum) * (*pnum);
    uint32_t* rw = (uint32_t*)run8;
    for (int i = tid; i < NBIN * BLK / 4; i += BLK) rw[i] = 0u;
    for (int i = tid; i < NBIN; i += BLK) soff[i] = (i < nt) ? g_offsets[i] : 0;
    __syncthreads();

    int g = blockIdx.x * BLK + tid;
    int s = g * SEG;
    int e = min(s + SEG, N);
    unsigned long long orderBase = 7ull * (unsigned long long)N + 2ull * (unsigned long long)nt;

    for (int p = s; p < e; p++) {
        int k = (int)g_tile8[p];
        unsigned char r = run8[k * BLK + tid]++;
        unsigned int po = (unsigned int)soff[k] + g_base[k * T_TOTAL + g] + (unsigned int)r;

        float2 xy = pos[p];
        float4 cv = cov[p];
        float a = cv.x, b = cv.y, c = cv.z, d = cv.w;
        float trace = a + d;
        float det = a * d - b * c;
        float t1 = 0.5f * trace;
        float disc = trace * trace - 4.0f * det;
        float t2 = 0.5f * sqrtf(fmaxf(disc, 0.0f));
        float radius = fmaxf(t1 - t2, t1 + t2);
        float inv = 1.0f / det;

        float* o = &out[(unsigned long long)po * 7ull];
        o[0] = xy.x;
        o[1] = xy.y;
        o[2] = d * inv;
        o[3] = -b * inv;
        o[4] = a * inv;
        o[5] = opac[p];
        o[6] = radius;
        out[orderBase + po] = (float)p;
    }
}

extern "C" void kernel_launch(void* const* d_in, const int* in_sizes, int n_in,
                              void* d_out, int out_size) {
    const float2* pos = (const float2*)d_in[0];
    const float4* cov = (const float4*)d_in[1];
    const float*  op  = (const float*)d_in[2];
    const int*    pnum = (const int*)d_in[3];
    int N = in_sizes[0] / 2;
    int SEG = (N + T_TOTAL - 1) / T_TOTAL;   // 123 for N=2e6 (fits uint8 counters)
    float* out = (float*)d_out;

    k1_tile<<<(N + 255) / 256, 256>>>(pos, pnum, N);
    k2_hist<<<GRID, BLK>>>(N, SEG);
    k5_scan<<<NBIN, 256>>>(pnum, N, out);
    k4_off<<<1, 256>>>(pnum, N, out);
    k6_scatter<<<GRID, BLK>>>(pos, cov, op, pnum, N, SEG, out);
}

// round 2
// speedup vs baseline: 2.4472x; 2.4472x over previous
#include <cuda_runtime.h>
#include <stdint.h>

// Stable counting sort by tile_id (<=256 bins), block-granular:
//  k_hist    : compute tile id (1B) + per-block 256-bin histogram
//  k_scan    : per-bin exclusive scan across blocks -> g_baseB, tile_counts
//  k_off     : exclusive scan over bins -> tile_offsets
//  k_scatter : stable within-block ranks via __match_any_sync + cross-warp
//              byte-count prefix (dp4a), stage locally-sorted permutation in
//              shared, emit features with coalesced (run-length ~16) writes.

#define NBIN   256
#define BLK    256
#define ROUNDS 16
#define CHUNK  (BLK * ROUNDS)                    // 4096 points / block
#define MAXN   2000000
#define MAXBLK ((MAXN + CHUNK - 1) / CHUNK)      // 489

__device__ unsigned char g_tile8[MAXN];
__device__ unsigned int  g_histB[NBIN * MAXBLK]; // [bin][blk]
__device__ unsigned int  g_baseB[NBIN * MAXBLK]; // exclusive prefix per bin
__device__ int g_counts [NBIN];
__device__ int g_offsets[NBIN];

// ---------------- K1+K2 fused: tile id + per-block histogram ----------------
__global__ void __launch_bounds__(BLK) k_hist(const float2* __restrict__ pos,
                                              const int* __restrict__ pnum,
                                              int N, int nblk) {
    __shared__ unsigned int cnt[NBIN];
    int tid = threadIdx.x;
    cnt[tid] = 0u;
    __syncthreads();
    int nt = *pnum;
    float ts = 1024.0f / (float)nt;
    int base = blockIdx.x * CHUNK;
    #pragma unroll
    for (int r = 0; r < ROUNDS; r++) {
        int p = base + r * BLK + tid;
        if (p < N) {
            float2 xy = pos[p];
            int tx = (int)floorf(xy.x / ts);
            int ty = (int)floorf(xy.y / ts);
            tx = min(max(tx, 0), nt - 1);
            ty = min(max(ty, 0), nt - 1);
            int k = ty * nt + tx;
            g_tile8[p] = (unsigned char)k;
            atomicAdd(&cnt[k], 1u);
        }
    }
    __syncthreads();
    g_histB[tid * nblk + blockIdx.x] = cnt[tid];
}

// ---------------- K5: per-bin exclusive scan across blocks ----------------
__global__ void __launch_bounds__(BLK) k_scan(const int* __restrict__ pnum,
                                              int N, int nblk,
                                              float* __restrict__ out) {
    const int IT = 2;                      // supports nblk <= 512 (MAXBLK=489)
    int bin = blockIdx.x;
    int tid = threadIdx.x;
    int base = bin * nblk;
    unsigned int v[IT];
    unsigned int s = 0;
    #pragma unroll
    for (int j = 0; j < IT; j++) {
        int idx = tid * IT + j;
        v[j] = (idx < nblk) ? g_histB[base + idx] : 0u;
        s += v[j];
    }
    __shared__ unsigned int sh[BLK];
    sh[tid] = s;
    __syncthreads();
    for (int off = 1; off < BLK; off <<= 1) {
        unsigned int x = (tid >= off) ? sh[tid - off] : 0u;
        __syncthreads();
        sh[tid] += x;
        __syncthreads();
    }
    unsigned int run = sh[tid] - s;
    #pragma unroll
    for (int j = 0; j < IT; j++) {
        int idx = tid * IT + j;
        if (idx < nblk) g_baseB[base + idx] = run;
        run += v[j];
    }
    if (tid == BLK - 1) {
        g_counts[bin] = (int)sh[BLK - 1];
        int nt2 = (*pnum) * (*pnum);
        if (bin < nt2)
            out[7ull * (unsigned long long)N + bin] = (float)sh[BLK - 1];
    }
}

// ---------------- K4: exclusive scan over bins -> tile_offsets ----------------
__global__ void __launch_bounds__(BLK) k_off(const int* __restrict__ pnum,
                                             int N, float* __restrict__ out) {
    int nt2 = (*pnum) * (*pnum);
    int tid = threadIdx.x;
    int v = (tid < nt2) ? g_counts[tid] : 0;
    __shared__ int sh[NBIN];
    sh[tid] = v;
    __syncthreads();
    for (int off = 1; off < BLK; off <<= 1) {
        int x = (tid >= off) ? sh[tid - off] : 0;
        __syncthreads();
        sh[tid] += x;
        __syncthreads();
    }
    int excl = sh[tid] - v;
    g_offsets[tid] = (tid < nt2) ? excl : 0;
    if (tid < nt2)
        out[7ull * (unsigned long long)N + nt2 + tid] = (float)excl;
}

// ---------------- K6: stable rank + staged coalesced scatter ----------------
__global__ void __launch_bounds__(BLK) k_scatter(
    const float2* __restrict__ pos, const float4* __restrict__ cov,
    const float* __restrict__ opac, const int* __restrict__ pnum,
    int N, int nblk, float* __restrict__ out)
{
    __shared__ unsigned char  sbin [CHUNK];     // 4KB
    __shared__ unsigned short srank[CHUNK];     // 8KB
    __shared__ unsigned short sslot[CHUNK];     // 8KB
    __shared__ unsigned char  wcnt [NBIN * 8];  // 2KB  per-round per-warp counts
    __shared__ unsigned int   baseRound[NBIN];  // 1KB  (reused as scan temp)
    __shared__ unsigned int   run  [NBIN];      // 1KB  running per-bin totals
    __shared__ unsigned int   binstart[NBIN];   // 1KB
    __shared__ unsigned int   sgb  [NBIN];      // 1KB  offsets[k] + baseB[k][blk]

    int tid  = threadIdx.x;
    int lane = tid & 31;
    int warp = tid >> 5;
    unsigned lt = (1u << lane) - 1u;
    int blk = blockIdx.x;
    int chunkStart = blk * CHUNK;
    int validCount = min(CHUNK, N - chunkStart);

    run[tid] = 0u;
    sgb[tid] = (unsigned)g_offsets[tid] + g_baseB[tid * nblk + blk];
    ((uint32_t*)wcnt)[tid]       = 0u;
    ((uint32_t*)wcnt)[tid + 256] = 0u;
    __syncthreads();

    // Phase A: stable within-block rank per point
    for (int r = 0; r < ROUNDS; r++) {
        int local = r * BLK + tid;
        int p = chunkStart + local;
        int k = (p < N) ? (int)g_tile8[p] : 256;
        unsigned mask = __match_any_sync(0xffffffffu, k);
        int rank_w = __popc(mask & lt);
        int grp    = __popc(mask);
        if (rank_w == 0 && k < 256) wcnt[k * 8 + warp] = (unsigned char)grp;
        __syncthreads();
        {   // bin owner (tid = bin): per-round base & running total
            const uint32_t* w = (const uint32_t*)&wcnt[tid * 8];
            unsigned tot = __dp4a(w[0], 0x01010101u, 0u);
            tot          = __dp4a(w[1], 0x01010101u, tot);
            baseRound[tid] = run[tid];
            run[tid] += tot;
        }
        __syncthreads();
        if (k < 256) {
            const uint32_t* w = (const uint32_t*)&wcnt[k * 8];
            unsigned m0, m1;
            if (warp >= 4) {
                m0 = 0xffffffffu;
                m1 = (warp == 4) ? 0u : (0xffffffffu >> ((8 - warp) * 8));
            } else {
                m0 = (warp == 0) ? 0u : (0xffffffffu >> ((4 - warp) * 8));
                m1 = 0u;
            }
            unsigned pre = __dp4a(w[0] & m0, 0x01010101u, 0u);
            pre          = __dp4a(w[1] & m1, 0x01010101u, pre);
            unsigned rk = baseRound[k] + pre + (unsigned)rank_w;
            sbin [local] = (unsigned char)k;
            srank[local] = (unsigned short)rk;
        }
        __syncthreads();
        ((uint32_t*)wcnt)[tid]       = 0u;   // re-zero for next round
        ((uint32_t*)wcnt)[tid + 256] = 0u;
        __syncthreads();
    }

    // Block histogram now in run[]; exclusive scan -> binstart (reuse baseRound)
    {
        unsigned v = run[tid];
        baseRound[tid] = v;
        __syncthreads();
        for (int off = 1; off < BLK; off <<= 1) {
            unsigned x = (tid >= off) ? baseRound[tid - off] : 0u;
            __syncthreads();
            baseRound[tid] += x;
            __syncthreads();
        }
        binstart[tid] = baseRound[tid] - v;
    }
    __syncthreads();

    // Phase B: scatter local indices into bin-sorted slots
    #pragma unroll
    for (int r = 0; r < ROUNDS; r++) {
        int local = r * BLK + tid;
        if (local < validCount)
            sslot[binstart[sbin[local]] + srank[local]] = (unsigned short)local;
    }
    __syncthreads();

    // Phase C: emit features/order with coalesced writes
    int nt2 = (*pnum) * (*pnum);
    unsigned long long orderBase =
        7ull * (unsigned long long)N + 2ull * (unsigned long long)nt2;
    for (int j = tid; j < validCount; j += BLK) {
        int li = (int)sslot[j];
        int k  = (int)sbin[li];
        int p  = chunkStart + li;
        unsigned po = sgb[k] + (unsigned)(j - (int)binstart[k]);

        float2 xy = pos[p];
        float4 cv = cov[p];
        float op  = opac[p];
        float a = cv.x, b = cv.y, c = cv.z, d = cv.w;
        float trace = a + d;
        float det   = a * d - b * c;
        float t1 = 0.5f * trace;
        float disc = trace * trace - 4.0f * det;
        float t2 = 0.5f * sqrtf(fmaxf(disc, 0.0f));
        float radius = fmaxf(t1 - t2, t1 + t2);
        float inv = 1.0f / det;

        float* o = out + (unsigned long long)po * 7ull;
        o[0] = xy.x;
        o[1] = xy.y;
        o[2] = d * inv;
        o[3] = -b * inv;
        o[4] = a * inv;
        o[5] = op;
        o[6] = radius;
        out[orderBase + po] = (float)p;
    }
}

extern "C" void kernel_launch(void* const* d_in, const int* in_sizes, int n_in,
                              void* d_out, int out_size) {
    const float2* pos  = (const float2*)d_in[0];
    const float4* cov  = (const float4*)d_in[1];
    const float*  op   = (const float*)d_in[2];
    const int*    pnum = (const int*)d_in[3];
    int N = in_sizes[0] / 2;
    int nblk = (N + CHUNK - 1) / CHUNK;
    float* out = (float*)d_out;

    k_hist   <<<nblk, BLK>>>(pos, pnum, N, nblk);
    k_scan   <<<NBIN, BLK>>>(pnum, N, nblk, out);
    k_off    <<<1,    BLK>>>(pnum, N, out);
    k_scatter<<<nblk, BLK>>>(pos, cov, op, pnum, N, nblk, out);
}

// round 3
// speedup vs baseline: 2.4907x; 1.0178x over previous
#include <cuda_runtime.h>
#include <stdint.h>

// Stable counting sort by tile_id (<=256 bins), block-granular, warp-private ranking:
//  k_hist    : tile id (1B) + per-block 256-bin histogram
//  k_scan    : per-bin exclusive scan across blocks -> g_baseB, tile_counts
//  k_off     : exclusive scan over bins -> tile_offsets
//  k_scatter : each warp owns 512 contiguous points; stable within-warp ranks via
//              __match_any_sync + warp-private shared counters (NO block barriers
//              in the main loop); per-bin 8-way warp prefix; staged coalesced emit.

#define NBIN   256
#define BLK    256
#define NW     8                                 // warps per block
#define WSEG   512                               // points per warp
#define ROUNDS 16                                // WSEG / 32
#define CHUNK  (NW * WSEG)                       // 4096 points / block
#define MAXN   2000000
#define MAXBLK ((MAXN + CHUNK - 1) / CHUNK)      // 489

__device__ unsigned char g_tile8[MAXN];
__device__ unsigned int  g_histB[NBIN * MAXBLK]; // [bin][blk]
__device__ unsigned int  g_baseB[NBIN * MAXBLK]; // exclusive prefix per bin
__device__ int g_counts [NBIN];
__device__ int g_offsets[NBIN];

// ---------------- K1+K2 fused: tile id + per-block histogram ----------------
__global__ void __launch_bounds__(BLK) k_hist(const float2* __restrict__ pos,
                                              const int* __restrict__ pnum,
                                              int N, int nblk) {
    __shared__ unsigned int cnt[NBIN];
    int tid = threadIdx.x;
    cnt[tid] = 0u;
    __syncthreads();
    int nt = *pnum;
    float ts = 1024.0f / (float)nt;
    int base = blockIdx.x * CHUNK;
    #pragma unroll
    for (int r = 0; r < ROUNDS; r++) {
        int p = base + r * BLK + tid;
        if (p < N) {
            float2 xy = pos[p];
            int tx = (int)floorf(xy.x / ts);
            int ty = (int)floorf(xy.y / ts);
            tx = min(max(tx, 0), nt - 1);
            ty = min(max(ty, 0), nt - 1);
            int k = ty * nt + tx;
            g_tile8[p] = (unsigned char)k;
            atomicAdd(&cnt[k], 1u);
        }
    }
    __syncthreads();
    g_histB[tid * nblk + blockIdx.x] = cnt[tid];
}

// ---------------- per-bin exclusive scan across blocks ----------------
__global__ void __launch_bounds__(BLK) k_scan(const int* __restrict__ pnum,
                                              int N, int nblk,
                                              float* __restrict__ out) {
    const int IT = 2;                      // nblk <= 512
    int bin = blockIdx.x;
    int tid = threadIdx.x;
    int base = bin * nblk;
    unsigned int v[IT];
    unsigned int s = 0;
    #pragma unroll
    for (int j = 0; j < IT; j++) {
        int idx = tid * IT + j;
        v[j] = (idx < nblk) ? g_histB[base + idx] : 0u;
        s += v[j];
    }
    __shared__ unsigned int sh[BLK];
    sh[tid] = s;
    __syncthreads();
    for (int off = 1; off < BLK; off <<= 1) {
        unsigned int x = (tid >= off) ? sh[tid - off] : 0u;
        __syncthreads();
        sh[tid] += x;
        __syncthreads();
    }
    unsigned int run = sh[tid] - s;
    #pragma unroll
    for (int j = 0; j < IT; j++) {
        int idx = tid * IT + j;
        if (idx < nblk) g_baseB[base + idx] = run;
        run += v[j];
    }
    if (tid == BLK - 1) {
        g_counts[bin] = (int)sh[BLK - 1];
        int nt2 = (*pnum) * (*pnum);
        if (bin < nt2)
            out[7ull * (unsigned long long)N + bin] = (float)sh[BLK - 1];
    }
}

// ---------------- exclusive scan over bins -> tile_offsets ----------------
__global__ void __launch_bounds__(BLK) k_off(const int* __restrict__ pnum,
                                             int N, float* __restrict__ out) {
    int nt2 = (*pnum) * (*pnum);
    int tid = threadIdx.x;
    int v = (tid < nt2) ? g_counts[tid] : 0;
    __shared__ int sh[NBIN];
    sh[tid] = v;
    __syncthreads();
    for (int off = 1; off < BLK; off <<= 1) {
        int x = (tid >= off) ? sh[tid - off] : 0;
        __syncthreads();
        sh[tid] += x;
        __syncthreads();
    }
    int excl = sh[tid] - v;
    g_offsets[tid] = (tid < nt2) ? excl : 0;
    if (tid < nt2)
        out[7ull * (unsigned long long)N + nt2 + tid] = (float)excl;
}

// ---------------- stable rank + staged coalesced scatter ----------------
__global__ void __launch_bounds__(BLK) k_scatter(
    const float2* __restrict__ pos, const float4* __restrict__ cov,
    const float* __restrict__ opac, const int* __restrict__ pnum,
    int N, int nblk, float* __restrict__ out)
{
    __shared__ unsigned char  sbin [CHUNK];        // 4KB
    __shared__ unsigned short srank[CHUNK];        // 8KB within-warp rank
    __shared__ unsigned short sslot[CHUNK];        // 8KB
    __shared__ unsigned int   wcnt [NW * NBIN];    // 8KB warp-private counters -> warp base
    __shared__ unsigned int   run  [NBIN];         // 1KB per-bin block totals
    __shared__ unsigned int   binstart[NBIN];      // 1KB
    __shared__ unsigned int   sgb  [NBIN];         // 1KB offsets[k] + baseB[k][blk]

    int tid  = threadIdx.x;
    int lane = tid & 31;
    int warp = tid >> 5;
    unsigned lt = (1u << lane) - 1u;
    int blk = blockIdx.x;
    int chunkStart = blk * CHUNK;
    int validCount = min(CHUNK, N - chunkStart);

    sgb[tid] = (unsigned)g_offsets[tid] + g_baseB[tid * nblk + blk];
    #pragma unroll
    for (int i = 0; i < NW; i++) wcnt[i * BLK + tid] = 0u;
    __syncthreads();

    // Phase A: stable within-warp ranks, warp-synchronous only (no block barriers)
    unsigned int* mycnt = &wcnt[warp * NBIN];
    #pragma unroll
    for (int r = 0; r < ROUNDS; r++) {
        int local = warp * WSEG + r * 32 + lane;
        int p = chunkStart + local;
        int k = (p < N) ? (int)g_tile8[p] : 300;
        unsigned mask = __match_any_sync(0xffffffffu, k);
        int leader = __ffs(mask) - 1;
        int rank_w = __popc(mask & lt);
        unsigned base = 0u;
        if (lane == leader && k < 256) {
            base = mycnt[k];
            mycnt[k] = base + (unsigned)__popc(mask);
        }
        base = __shfl_sync(0xffffffffu, base, leader);
        if (k < 256) {
            sbin [local] = (unsigned char)k;
            srank[local] = (unsigned short)(base + (unsigned)rank_w);
        }
    }
    __syncthreads();

    // Combine: per-bin exclusive prefix over warps (in place) + block totals
    {
        unsigned s = 0u;
        #pragma unroll
        for (int w = 0; w < NW; w++) {
            unsigned c = wcnt[w * NBIN + tid];
            wcnt[w * NBIN + tid] = s;
            s += c;
        }
        run[tid] = s;
    }
    __syncthreads();

    // Exclusive scan over bins -> binstart
    {
        unsigned v = run[tid];
        binstart[tid] = v;
        __syncthreads();
        for (int off = 1; off < BLK; off <<= 1) {
            unsigned x = (tid >= off) ? binstart[tid - off] : 0u;
            __syncthreads();
            binstart[tid] += x;
            __syncthreads();
        }
        binstart[tid] -= v;
    }
    __syncthreads();

    // Phase B: scatter local indices into bin-sorted slots
    #pragma unroll
    for (int r = 0; r < ROUNDS; r++) {
        int local = r * BLK + tid;
        if (local < validCount) {
            int k = (int)sbin[local];
            unsigned pos_local = binstart[k] + wcnt[(local >> 9) * NBIN + k]
                               + (unsigned)srank[local];
            sslot[pos_local] = (unsigned short)local;
        }
    }
    __syncthreads();

    // Phase C: emit features/order with coalesced writes
    int nt2 = (*pnum) * (*pnum);
    unsigned long long orderBase =
        7ull * (unsigned long long)N + 2ull * (unsigned long long)nt2;
    for (int j = tid; j < validCount; j += BLK) {
        int li = (int)sslot[j];
        int k  = (int)sbin[li];
        int p  = chunkStart + li;
        unsigned po = sgb[k] + (unsigned)(j - (int)binstart[k]);

        float2 xy = pos[p];
        float4 cv = cov[p];
        float op  = opac[p];
        float a = cv.x, b = cv.y, c = cv.z, d = cv.w;
        float trace = a + d;
        float det   = a * d - b * c;
        float t1 = 0.5f * trace;
        float disc = trace * trace - 4.0f * det;
        float t2 = 0.5f * sqrtf(fmaxf(disc, 0.0f));
        float radius = fmaxf(t1 - t2, t1 + t2);
        float inv = 1.0f / det;

        float* o = out + (unsigned long long)po * 7ull;
        o[0] = xy.x;
        o[1] = xy.y;
        o[2] = d * inv;
        o[3] = -b * inv;
        o[4] = a * inv;
        o[5] = op;
        o[6] = radius;
        out[orderBase + po] = (float)p;
    }
}

extern "C" void kernel_launch(void* const* d_in, const int* in_sizes, int n_in,
                              void* d_out, int out_size) {
    const float2* pos  = (const float2*)d_in[0];
    const float4* cov  = (const float4*)d_in[1];
    const float*  op   = (const float*)d_in[2];
    const int*    pnum = (const int*)d_in[3];
    int N = in_sizes[0] / 2;
    int nblk = (N + CHUNK - 1) / CHUNK;
    float* out = (float*)d_out;

    k_hist   <<<nblk, BLK>>>(pos, pnum, N, nblk);
    k_scan   <<<NBIN, BLK>>>(pnum, N, nblk, out);
    k_off    <<<1,    BLK>>>(pnum, N, out);
    k_scatter<<<nblk, BLK>>>(pos, cov, op, pnum, N, nblk, out);
}

// round 4
// speedup vs baseline: 2.9868x; 1.1992x over previous
#include <cuda_runtime.h>
#include <stdint.h>

// Stable counting sort by tile_id (<=256 bins).
//  k_hist    : tile id (1B) + per-block 256-bin histogram
//  k_scan    : per-bin exclusive scan across blocks -> g_baseB, tile_counts
//  k_off     : exclusive scan over bins -> tile_offsets
//  k_scatter : warp-private stable ranks held in REGISTERS (no shared staging),
//              combine to absolute per-(warp,bin) bases, then coalesced input
//              reads + scattered fire-and-forget writes.

#define NBIN   256
#define BLK    256
#define NW     8                                 // warps per block
#define WSEG   256                               // points per warp
#define ROUNDS 8                                 // WSEG / 32
#define CHUNK  (NW * WSEG)                       // 2048 points / block
#define MAXN   2000000
#define MAXBLK ((MAXN + CHUNK - 1) / CHUNK)      // 977

__device__ unsigned char g_tile8[MAXN];
__device__ unsigned int  g_histB[NBIN * MAXBLK]; // [bin][blk]
__device__ unsigned int  g_baseB[NBIN * MAXBLK]; // exclusive prefix per bin
__device__ int g_counts [NBIN];
__device__ int g_offsets[NBIN];

// ---------------- tile id + per-block histogram ----------------
__global__ void __launch_bounds__(BLK) k_hist(const float2* __restrict__ pos,
                                              const int* __restrict__ pnum,
                                              int N, int nblk) {
    __shared__ unsigned int cnt[NBIN];
    int tid = threadIdx.x;
    cnt[tid] = 0u;
    __syncthreads();
    int nt = *pnum;
    float ts = 1024.0f / (float)nt;
    int base = blockIdx.x * CHUNK;
    #pragma unroll
    for (int r = 0; r < ROUNDS; r++) {
        int p = base + r * BLK + tid;
        if (p < N) {
            float2 xy = pos[p];
            int tx = (int)floorf(xy.x / ts);
            int ty = (int)floorf(xy.y / ts);
            tx = min(max(tx, 0), nt - 1);
            ty = min(max(ty, 0), nt - 1);
            int k = ty * nt + tx;
            g_tile8[p] = (unsigned char)k;
            atomicAdd(&cnt[k], 1u);
        }
    }
    __syncthreads();
    g_histB[tid * nblk + blockIdx.x] = cnt[tid];
}

// ---------------- per-bin exclusive scan across blocks ----------------
__global__ void __launch_bounds__(BLK) k_scan(const int* __restrict__ pnum,
                                              int N, int nblk,
                                              float* __restrict__ out) {
    const int IT = 4;                      // nblk <= 1024
    int bin = blockIdx.x;
    int tid = threadIdx.x;
    int base = bin * nblk;
    unsigned int v[IT];
    unsigned int s = 0;
    #pragma unroll
    for (int j = 0; j < IT; j++) {
        int idx = tid * IT + j;
        v[j] = (idx < nblk) ? g_histB[base + idx] : 0u;
        s += v[j];
    }
    __shared__ unsigned int sh[BLK];
    sh[tid] = s;
    __syncthreads();
    for (int off = 1; off < BLK; off <<= 1) {
        unsigned int x = (tid >= off) ? sh[tid - off] : 0u;
        __syncthreads();
        sh[tid] += x;
        __syncthreads();
    }
    unsigned int run = sh[tid] - s;
    #pragma unroll
    for (int j = 0; j < IT; j++) {
        int idx = tid * IT + j;
        if (idx < nblk) g_baseB[base + idx] = run;
        run += v[j];
    }
    if (tid == BLK - 1) {
        g_counts[bin] = (int)sh[BLK - 1];
        int nt2 = (*pnum) * (*pnum);
        if (bin < nt2)
            out[7ull * (unsigned long long)N + bin] = (float)sh[BLK - 1];
    }
}

// ---------------- exclusive scan over bins -> tile_offsets ----------------
__global__ void __launch_bounds__(BLK) k_off(const int* __restrict__ pnum,
                                             int N, float* __restrict__ out) {
    int nt2 = (*pnum) * (*pnum);
    int tid = threadIdx.x;
    int v = (tid < nt2) ? g_counts[tid] : 0;
    __shared__ int sh[NBIN];
    sh[tid] = v;
    __syncthreads();
    for (int off = 1; off < BLK; off <<= 1) {
        int x = (tid >= off) ? sh[tid - off] : 0;
        __syncthreads();
        sh[tid] += x;
        __syncthreads();
    }
    int excl = sh[tid] - v;
    g_offsets[tid] = (tid < nt2) ? excl : 0;
    if (tid < nt2)
        out[7ull * (unsigned long long)N + nt2 + tid] = (float)excl;
}

// ---------------- stable rank (registers) + coalesced-read scatter ----------------
__global__ void __launch_bounds__(BLK) k_scatter(
    const float2* __restrict__ pos, const float4* __restrict__ cov,
    const float* __restrict__ opac, const int* __restrict__ pnum,
    int N, int nblk, float* __restrict__ out)
{
    __shared__ unsigned int wbase[NW * NBIN];   // 8KB: counts -> absolute bases

    int tid  = threadIdx.x;
    int lane = tid & 31;
    int warp = tid >> 5;
    unsigned lt = (1u << lane) - 1u;
    int blk = blockIdx.x;
    int chunkStart = blk * CHUNK;

    #pragma unroll
    for (int i = 0; i < NW; i++) wbase[i * NBIN + tid] = 0u;
    __syncthreads();

    // Phase A: stable within-warp ranks, (rank,bin) kept in registers
    unsigned int* mycnt = &wbase[warp * NBIN];
    unsigned packed[ROUNDS];
    #pragma unroll
    for (int r = 0; r < ROUNDS; r++) {
        int local = warp * WSEG + r * 32 + lane;
        int p = chunkStart + local;
        int k = (p < N) ? (int)g_tile8[p] : 300;
        unsigned mask = __match_any_sync(0xffffffffu, k);
        int leader = __ffs(mask) - 1;
        int rank_w = __popc(mask & lt);
        unsigned base = 0u;
        if (lane == leader && k < 256) {
            base = mycnt[k];
            mycnt[k] = base + (unsigned)__popc(mask);
        }
        base = __shfl_sync(0xffffffffu, base, leader);
        packed[r] = ((base + (unsigned)rank_w) << 16) | (unsigned)(k & 0xff);
    }
    __syncthreads();

    // Combine: absolute base per (warp,bin) = offsets[bin] + baseB[bin][blk] + warp prefix
    {
        unsigned s = (unsigned)g_offsets[tid] + g_baseB[tid * nblk + blk];
        #pragma unroll
        for (int w = 0; w < NW; w++) {
            unsigned c = wbase[w * NBIN + tid];
            wbase[w * NBIN + tid] = s;
            s += c;
        }
    }
    __syncthreads();

    // Phase C: coalesced input reads, scattered (non-blocking) writes
    int nt2 = (*pnum) * (*pnum);
    unsigned long long orderBase =
        7ull * (unsigned long long)N + 2ull * (unsigned long long)nt2;
    const unsigned int* mybase = &wbase[warp * NBIN];
    #pragma unroll
    for (int r = 0; r < ROUNDS; r++) {
        int local = warp * WSEG + r * 32 + lane;
        int p = chunkStart + local;
        if (p < N) {
            int k = (int)(packed[r] & 0xffu);
            unsigned po = mybase[k] + (packed[r] >> 16);

            float2 xy = pos[p];
            float4 cv = cov[p];
            float op  = opac[p];
            float a = cv.x, b = cv.y, c = cv.z, d = cv.w;
            float trace = a + d;
            float det   = a * d - b * c;
            float t1 = 0.5f * trace;
            float disc = trace * trace - 4.0f * det;
            float t2 = 0.5f * sqrtf(fmaxf(disc, 0.0f));
            float radius = fmaxf(t1 - t2, t1 + t2);
            float inv = 1.0f / det;

            float* o = out + (unsigned long long)po * 7ull;
            o[0] = xy.x;
            o[1] = xy.y;
            o[2] = d * inv;
            o[3] = -b * inv;
            o[4] = a * inv;
            o[5] = op;
            o[6] = radius;
            out[orderBase + po] = (float)p;
        }
    }
}

extern "C" void kernel_launch(void* const* d_in, const int* in_sizes, int n_in,
                              void* d_out, int out_size) {
    const float2* pos  = (const float2*)d_in[0];
    const float4* cov  = (const float4*)d_in[1];
    const float*  op   = (const float*)d_in[2];
    const int*    pnum = (const int*)d_in[3];
    int N = in_sizes[0] / 2;
    int nblk = (N + CHUNK - 1) / CHUNK;
    float* out = (float*)d_out;

    k_hist   <<<nblk, BLK>>>(pos, pnum, N, nblk);
    k_scan   <<<NBIN, BLK>>>(pnum, N, nblk, out);
    k_off    <<<1,    BLK>>>(pnum, N, out);
    k_scatter<<<nblk, BLK>>>(pos, cov, op, pnum, N, nblk, out);
}